// round 5
// baseline (speedup 1.0000x reference)
#include <cuda_runtime.h>

#define N_NODES 50000
#define E_EDGES 800000
#define IN_DIM  128
#define OUT_DIM 64
#define HEADS   4
#define HC      256      // HEADS*OUT_DIM
#define Q_HID   32
#define NEG_SLOPE 0.2f

// ---------------- scratch (static device memory; no allocations) ----------------
__device__ __align__(16) float g_h[N_NODES * HC];   // 51.2 MB  h = x@W
__device__ float g_asrc[N_NODES * HEADS];
__device__ float g_adst[N_NODES * HEADS];
__device__ __align__(16) float g_ex[E_EDGES * HEADS];
__device__ float g_acc[N_NODES * OUT_DIM];
__device__ __align__(16) float g_v[64 * HEADS];     // W_edge contracted with att_edge
__device__ __align__(16) float g_wq2v[Q_HID * HEADS];
__device__ float g_bq2v[HEADS];
__device__ float g_t[OUT_DIM];
__device__ int   g_src[E_EDGES];
__device__ int   g_dst[E_EDGES];
// CSR by destination
__device__ int   g_cnt[N_NODES];
__device__ int   g_rowptr[N_NODES + 1];
__device__ int   g_cur[N_NODES];
__device__ int   g_eid[E_EDGES];

// ---------------- K_convert: detect int32/int64 + expand + zero counters -----
__global__ void k_convert(const void* __restrict__ ei) {
    __shared__ int s_is64;
    if (threadIdx.x == 0) {
        // int64 values < 2^31 -> odd 32-bit words all zero; int32 data -> random ids
        const int* p = (const int*)ei;
        int zeros = 0;
        for (int i = 1; i < 256; i += 2) zeros += (p[i] == 0);
        s_is64 = (zeros > 64);
    }
    __syncthreads();
    int e = blockIdx.x * blockDim.x + threadIdx.x;
    if (e < N_NODES) g_cnt[e] = 0;   // zero histogram counters
    if (e >= E_EDGES) return;
    if (s_is64) {
        const long long* p = (const long long*)ei;
        g_src[e] = (int)p[e];
        g_dst[e] = (int)p[E_EDGES + e];
    } else {
        const int* p = (const int*)ei;
        g_src[e] = p[e];
        g_dst[e] = p[E_EDGES + e];
    }
}

// ---------------- K_hist ------------------------------------------------------
__global__ void k_hist() {
    int e = blockIdx.x * blockDim.x + threadIdx.x;
    if (e < E_EDGES) atomicAdd(&g_cnt[g_dst[e]], 1);
}

// ---------------- K_scan: exclusive prefix (single 1024-thread block) --------
__global__ void k_scan() {
    __shared__ int part[1024];
    const int CH = (N_NODES + 1023) / 1024;  // 49
    int t = threadIdx.x;
    int base = t * CH;
    int lim = N_NODES - base; if (lim > CH) lim = CH; if (lim < 0) lim = 0;
    int s = 0;
    for (int i = 0; i < lim; ++i) s += g_cnt[base + i];
    part[t] = s;
    __syncthreads();
    // Hillis-Steele inclusive scan
    for (int off = 1; off < 1024; off <<= 1) {
        int v = (t >= off) ? part[t - off] : 0;
        __syncthreads();
        part[t] += v;
        __syncthreads();
    }
    int run = part[t] - s;  // exclusive prefix of this chunk
    for (int i = 0; i < lim; ++i) {
        int idx = base + i;
        g_rowptr[idx] = run;
        g_cur[idx] = run;
        run += g_cnt[idx];
    }
    if (t == 1023) g_rowptr[N_NODES] = E_EDGES;
}

// ---------------- K_scatter ---------------------------------------------------
__global__ void k_scatter() {
    int e = blockIdx.x * blockDim.x + threadIdx.x;
    if (e >= E_EDGES) return;
    int pos = atomicAdd(&g_cur[g_dst[e]], 1);
    g_eid[pos] = e;
}

// ---------------- K0: tiny precomputes (one block) ----------------
__global__ void k0_precompute(const float* __restrict__ W_edge,
                              const float* __restrict__ att_edge,
                              const float* __restrict__ Wq2,
                              const float* __restrict__ bq2,
                              const float* __restrict__ ns,
                              const float* __restrict__ Wc,
                              const float* __restrict__ bc) {
    int t = threadIdx.x; // 256 threads
    {   // v[d][hd] = sum_c W_edge[d, hd*64+c] * att_edge[hd, c]
        int d = t >> 2, hd = t & 3;
        float s = 0.f;
        #pragma unroll 8
        for (int c = 0; c < 64; ++c)
            s += W_edge[d * HC + hd * 64 + c] * att_edge[hd * 64 + c];
        g_v[t] = s;
    }
    __syncthreads();
    if (t < Q_HID * HEADS) {   // Wq2v[j][hd] = sum_d Wq2[j,d] * v[d][hd]
        int j = t >> 2, hd = t & 3;
        float s = 0.f;
        #pragma unroll 8
        for (int d = 0; d < 64; ++d)
            s += Wq2[j * 64 + d] * g_v[d * 4 + hd];
        g_wq2v[t] = s;
    }
    if (t >= 128 && t < 128 + HEADS) {
        int hd = t - 128;
        float s = 0.f;
        for (int d = 0; d < 64; ++d) s += bq2[d] * g_v[d * 4 + hd];
        g_bq2v[hd] = s;
    }
    if (t >= 192) {            // t[j] = bc[j] + sum_k ns[k]*Wc[64+k, j]
        int j = t - 192;
        float s = bc[j];
        #pragma unroll
        for (int k = 0; k < 8; ++k) s += ns[k] * Wc[(64 + k) * 64 + j];
        g_t[j] = s;
    }
}

// ---------------- K1: h = x @ W  (50000x128 @ 128x256) ----------------
__global__ void k1_gemm_h(const float* __restrict__ x, const float* __restrict__ W) {
    __shared__ float xs[IN_DIM * 16]; // transposed: xs[k*16 + m]
    int t = threadIdx.x;
    int n0 = blockIdx.x * 16;
    #pragma unroll
    for (int u = 0; u < 8; ++u) {
        int i = t + u * 256;
        int m = i >> 7, k = i & 127;
        xs[k * 16 + m] = x[(n0 + m) * IN_DIM + k];
    }
    __syncthreads();
    float acc[16];
    #pragma unroll
    for (int m = 0; m < 16; ++m) acc[m] = 0.f;
    #pragma unroll 4
    for (int k = 0; k < IN_DIM; ++k) {
        float w = W[k * HC + t];
        const float4* xp = (const float4*)(&xs[k * 16]);
        float4 a0 = xp[0], a1 = xp[1], a2 = xp[2], a3 = xp[3];
        acc[0]  += a0.x * w; acc[1]  += a0.y * w; acc[2]  += a0.z * w; acc[3]  += a0.w * w;
        acc[4]  += a1.x * w; acc[5]  += a1.y * w; acc[6]  += a1.z * w; acc[7]  += a1.w * w;
        acc[8]  += a2.x * w; acc[9]  += a2.y * w; acc[10] += a2.z * w; acc[11] += a2.w * w;
        acc[12] += a3.x * w; acc[13] += a3.y * w; acc[14] += a3.z * w; acc[15] += a3.w * w;
    }
    #pragma unroll
    for (int m = 0; m < 16; ++m)
        g_h[(n0 + m) * HC + t] = acc[m];
}

// ---------------- K1b: a_src/a_dst per node/head (warp per node) --------------
__global__ void k1b_attn(const float* __restrict__ att_src,
                         const float* __restrict__ att_dst) {
    int warp = (blockIdx.x * blockDim.x + threadIdx.x) >> 5;
    int lane = threadIdx.x & 31;
    if (warp >= N_NODES) return;
    const float* hrow = &g_h[warp * HC];
    float s[HEADS], d[HEADS];
    #pragma unroll
    for (int hd = 0; hd < HEADS; ++hd) {
        float h1 = hrow[hd * 64 + lane], h2 = hrow[hd * 64 + 32 + lane];
        float as1 = att_src[hd * 64 + lane], as2 = att_src[hd * 64 + 32 + lane];
        float ad1 = att_dst[hd * 64 + lane], ad2 = att_dst[hd * 64 + 32 + lane];
        float ps = h1 * as1 + h2 * as2;
        float pd = h1 * ad1 + h2 * ad2;
        #pragma unroll
        for (int o = 16; o > 0; o >>= 1) {
            ps += __shfl_xor_sync(0xffffffffu, ps, o);
            pd += __shfl_xor_sync(0xffffffffu, pd, o);
        }
        s[hd] = ps; d[hd] = pd;
    }
    if (lane == 0) {
        #pragma unroll
        for (int hd = 0; hd < HEADS; ++hd) {
            g_asrc[warp * HEADS + hd] = s[hd];
            g_adst[warp * HEADS + hd] = d[hd];
        }
    }
}

// ---------------- K2: edge pass — alpha logits -> exp (warp per edge) ---------
__global__ void k2_edge(const float* __restrict__ edge_attr,
                        const float* __restrict__ pq,
                        const float* __restrict__ Wq1,
                        const float* __restrict__ bq1) {
    int warp = (blockIdx.x * blockDim.x + threadIdx.x) >> 5;
    int lane = threadIdx.x & 31;
    if (warp >= E_EDGES) return;
    int e = warp;
    int src = g_src[e];
    int dst = g_dst[e];

    float p0 = 0.f, p1 = 0.f, p2 = 0.f, p3 = 0.f;
    const float* ea = &edge_attr[(long long)e * 64];
    #pragma unroll
    for (int r = 0; r < 2; ++r) {
        int dd = lane + r * 32;
        float a = ea[dd];
        float4 v = *(const float4*)&g_v[dd * 4];
        p0 += a * v.x; p1 += a * v.y; p2 += a * v.z; p3 += a * v.w;
    }
    // path-quality MLP, hidden unit j = lane (Q_HID == 32)
    float q0 = pq[e * 4 + 0] * 0.01f;
    float q1 = pq[e * 4 + 1] * 0.01f;
    float q2 = pq[e * 4 + 2] * 100.f;
    float q3 = pq[e * 4 + 3] * 100.f;
    float hj = q0 * Wq1[lane] + q1 * Wq1[32 + lane]
             + q2 * Wq1[64 + lane] + q3 * Wq1[96 + lane] + bq1[lane];
    hj = fmaxf(hj, 0.f);
    {
        float4 w = *(const float4*)&g_wq2v[lane * 4];
        p0 += hj * w.x; p1 += hj * w.y; p2 += hj * w.z; p3 += hj * w.w;
    }
    #pragma unroll
    for (int o = 16; o > 0; o >>= 1) {
        p0 += __shfl_xor_sync(0xffffffffu, p0, o);
        p1 += __shfl_xor_sync(0xffffffffu, p1, o);
        p2 += __shfl_xor_sync(0xffffffffu, p2, o);
        p3 += __shfl_xor_sync(0xffffffffu, p3, o);
    }
    // butterfly => all lanes hold all 4 head sums; lanes 0..3 finish one head each
    if (lane < 4) {
        float pe = (lane == 0) ? p0 : (lane == 1) ? p1 : (lane == 2) ? p2 : p3;
        float a = g_asrc[src * HEADS + lane] + g_adst[dst * HEADS + lane]
                + pe + g_bq2v[lane];
        a = (a > 0.f) ? a : NEG_SLOPE * a;   // leaky_relu
        g_ex[e * HEADS + lane] = expf(a);    // max-shift omitted: identical softmax
    }
}

// ---------------- K4b: CSR pull aggregate (warp per dst node, no atomics) -----
// acc[n][c] = sum_h (0.25/den_h) * sum_{e in row(n)} ex[e,h] * h[src_e, h, c]
__global__ void k4b_aggregate() {
    int warp = (blockIdx.x * blockDim.x + threadIdx.x) >> 5;
    int lane = threadIdx.x & 31;
    if (warp >= N_NODES) return;
    int beg = __ldg(&g_rowptr[warp]), end = __ldg(&g_rowptr[warp + 1]);
    int c = lane * 2;

    float a0x = 0.f, a0y = 0.f, a1x = 0.f, a1y = 0.f;
    float a2x = 0.f, a2y = 0.f, a3x = 0.f, a3y = 0.f;
    float d0 = 0.f, d1 = 0.f, d2 = 0.f, d3 = 0.f;

    for (int base = beg; base < end; base += 32) {
        int n = end - base; if (n > 32) n = 32;
        int srcL = 0;
        float exx = 0.f, exy = 0.f, exz = 0.f, exw = 0.f;
        if (base + lane < end) {
            int eid = __ldg(&g_eid[base + lane]);
            srcL = __ldg(&g_src[eid]);
            float4 ex4 = *(const float4*)&g_ex[eid * 4];
            exx = ex4.x; exy = ex4.y; exz = ex4.z; exw = ex4.w;
        }
        for (int j = 0; j < n; ++j) {
            int   s  = __shfl_sync(0xffffffffu, srcL, j);
            float e0 = __shfl_sync(0xffffffffu, exx, j);
            float e1 = __shfl_sync(0xffffffffu, exy, j);
            float e2 = __shfl_sync(0xffffffffu, exz, j);
            float e3 = __shfl_sync(0xffffffffu, exw, j);
            d0 += e0; d1 += e1; d2 += e2; d3 += e3;
            const float* hb = &g_h[s * HC + c];
            float2 h0 = *(const float2*)&hb[0];
            float2 h1 = *(const float2*)&hb[64];
            float2 h2 = *(const float2*)&hb[128];
            float2 h3 = *(const float2*)&hb[192];
            a0x += e0 * h0.x; a0y += e0 * h0.y;
            a1x += e1 * h1.x; a1y += e1 * h1.y;
            a2x += e2 * h2.x; a2y += e2 * h2.y;
            a3x += e3 * h3.x; a3y += e3 * h3.y;
        }
    }
    float r0 = (d0 > 0.f) ? 0.25f / d0 : 0.f;
    float r1 = (d1 > 0.f) ? 0.25f / d1 : 0.f;
    float r2 = (d2 > 0.f) ? 0.25f / d2 : 0.f;
    float r3 = (d3 > 0.f) ? 0.25f / d3 : 0.f;
    float2 o;
    o.x = a0x * r0 + a1x * r1 + a2x * r2 + a3x * r3;
    o.y = a0y * r0 + a1y * r1 + a2y * r2 + a3y * r3;
    *(float2*)&g_acc[warp * OUT_DIM + c] = o;
}

// ---------------- K5: out = relu(x_conv @ Wc[:64] + t)  (4 nodes/block) -------
__global__ void k5_out(const float* __restrict__ Wc,
                       const float* __restrict__ bias,
                       float* __restrict__ out) {
    __shared__ float xc[4][OUT_DIM];
    int t = threadIdx.x;
    int nl = t >> 6, j = t & 63;
    int n = blockIdx.x * 4 + nl;
    xc[nl][j] = g_acc[n * OUT_DIM + j] + bias[j];
    __syncthreads();
    float s = g_t[j];
    #pragma unroll 8
    for (int c = 0; c < OUT_DIM; ++c)
        s += xc[nl][c] * Wc[c * 64 + j];
    out[n * OUT_DIM + j] = fmaxf(s, 0.f);
}

// ---------------- launch ----------------
extern "C" void kernel_launch(void* const* d_in, const int* in_sizes, int n_in,
                              void* d_out, int out_size) {
    const float* x         = (const float*)d_in[0];
    const void*  ei        = d_in[1];                 // int32 or int64, runtime-detected
    const float* edge_attr = (const float*)d_in[2];
    const float* pq        = (const float*)d_in[3];
    const float* ns        = (const float*)d_in[4];
    const float* W         = (const float*)d_in[5];
    const float* att_src   = (const float*)d_in[6];
    const float* att_dst   = (const float*)d_in[7];
    const float* W_edge    = (const float*)d_in[8];
    const float* att_edge  = (const float*)d_in[9];
    const float* bias      = (const float*)d_in[10];
    const float* Wq1       = (const float*)d_in[11];
    const float* bq1       = (const float*)d_in[12];
    const float* Wq2       = (const float*)d_in[13];
    const float* bq2       = (const float*)d_in[14];
    const float* Wc        = (const float*)d_in[15];
    const float* bc        = (const float*)d_in[16];
    float* out = (float*)d_out;

    k_convert<<<(E_EDGES + 255) / 256, 256>>>(ei);
    k_hist<<<(E_EDGES + 255) / 256, 256>>>();
    k_scan<<<1, 1024>>>();
    k_scatter<<<(E_EDGES + 255) / 256, 256>>>();
    k0_precompute<<<1, 256>>>(W_edge, att_edge, Wq2, bq2, ns, Wc, bc);
    k1_gemm_h<<<N_NODES / 16, 256>>>(x, W);
    k1b_attn<<<(N_NODES * 32 + 255) / 256, 256>>>(att_src, att_dst);
    k2_edge<<<E_EDGES / 8, 256>>>(edge_attr, pq, Wq1, bq1);
    k4b_aggregate<<<(N_NODES * 32 + 255) / 256, 256>>>();
    k5_out<<<N_NODES / 4, 256>>>(Wc, bias, out);
}

// round 6
// speedup vs baseline: 1.1701x; 1.1701x over previous
#include <cuda_runtime.h>
#include <cuda_fp16.h>

#define N_NODES 50000
#define E_EDGES 800000
#define IN_DIM  128
#define OUT_DIM 64
#define HEADS   4
#define HC      256      // HEADS*OUT_DIM
#define Q_HID   32
#define NEG_SLOPE 0.2f

// ---------------- scratch (static device memory; no allocations) ----------------
__device__ __align__(16) __half g_hh[N_NODES * HC];   // 25.6 MB  h = x@W (fp16 storage)
__device__ __align__(16) float g_asrc[N_NODES * HEADS];
__device__ __align__(16) float g_adst[N_NODES * HEADS];
__device__ __align__(16) float g_pe[E_EDGES * HEADS];  // per-edge attention logit part
__device__ __align__(16) float g_ex[E_EDGES * HEADS];  // exp(alpha)
__device__ __align__(16) float g_den[N_NODES * HEADS]; // den, then 0.25/den
__device__ __align__(16) float g_acc[N_NODES * OUT_DIM];
__device__ __align__(16) float g_v[64 * HEADS];        // W_edge contracted with att_edge
__device__ __align__(16) float g_wq2v[Q_HID * HEADS];
__device__ float g_bq2v[HEADS];
__device__ float g_t[OUT_DIM];
__device__ int   g_src[E_EDGES];
__device__ int   g_dst[E_EDGES];

// ---------------- K_convert: detect int32/int64, expand indices, zero acc/den --
__global__ void k_convert(const void* __restrict__ ei) {
    __shared__ int s_is64;
    if (threadIdx.x == 0) {
        // true int64 (< 2^31) -> odd 32-bit words all zero; int32 data -> random ids
        const int* p = (const int*)ei;
        int zeros = 0;
        for (int i = 1; i < 256; i += 2) zeros += (p[i] == 0);
        s_is64 = (zeros > 64);
    }
    __syncthreads();
    int i = blockIdx.x * blockDim.x + threadIdx.x;   // grid covers N_NODES*64
    if (i < N_NODES * OUT_DIM) g_acc[i] = 0.f;
    if (i < N_NODES * HEADS)   g_den[i] = 0.f;
    if (i < E_EDGES) {
        if (s_is64) {
            const long long* p = (const long long*)ei;
            g_src[i] = (int)p[i];
            g_dst[i] = (int)p[E_EDGES + i];
        } else {
            const int* p = (const int*)ei;
            g_src[i] = p[i];
            g_dst[i] = p[E_EDGES + i];
        }
    }
}

// ---------------- K0: tiny precomputes (one block) ----------------
__global__ void k0_precompute(const float* __restrict__ W_edge,
                              const float* __restrict__ att_edge,
                              const float* __restrict__ Wq2,
                              const float* __restrict__ bq2,
                              const float* __restrict__ ns,
                              const float* __restrict__ Wc,
                              const float* __restrict__ bc) {
    int t = threadIdx.x; // 256 threads
    {   // v[d][hd] = sum_c W_edge[d, hd*64+c] * att_edge[hd, c]
        int d = t >> 2, hd = t & 3;
        float s = 0.f;
        #pragma unroll 8
        for (int c = 0; c < 64; ++c)
            s += W_edge[d * HC + hd * 64 + c] * att_edge[hd * 64 + c];
        g_v[t] = s;
    }
    __syncthreads();
    if (t < Q_HID * HEADS) {   // Wq2v[j][hd] = sum_d Wq2[j,d] * v[d][hd]
        int j = t >> 2, hd = t & 3;
        float s = 0.f;
        #pragma unroll 8
        for (int d = 0; d < 64; ++d)
            s += Wq2[j * 64 + d] * g_v[d * 4 + hd];
        g_wq2v[t] = s;
    }
    if (t >= 128 && t < 128 + HEADS) {
        int hd = t - 128;
        float s = 0.f;
        for (int d = 0; d < 64; ++d) s += bq2[d] * g_v[d * 4 + hd];
        g_bq2v[hd] = s;
    }
    if (t >= 192) {            // t[j] = bc[j] + sum_k ns[k]*Wc[64+k, j]
        int j = t - 192;
        float s = bc[j];
        #pragma unroll
        for (int k = 0; k < 8; ++k) s += ns[k] * Wc[(64 + k) * 64 + j];
        g_t[j] = s;
    }
}

// ---------------- K2a: edge-local logits (runs BEFORE k1 so its 205MB stream ---
// cannot evict g_h from L2). Warp per edge; streamed loads (__ldcs).
__global__ void k2a_edge(const float* __restrict__ edge_attr,
                         const float* __restrict__ pq,
                         const float* __restrict__ Wq1,
                         const float* __restrict__ bq1) {
    int warp = (blockIdx.x * blockDim.x + threadIdx.x) >> 5;
    int lane = threadIdx.x & 31;
    if (warp >= E_EDGES) return;
    int e = warp;

    float p0 = 0.f, p1 = 0.f, p2 = 0.f, p3 = 0.f;
    const float* ea = &edge_attr[(long long)e * 64];
    #pragma unroll
    for (int r = 0; r < 2; ++r) {
        int dd = lane + r * 32;
        float a = __ldcs(&ea[dd]);                 // evict-first: pure stream
        float4 v = *(const float4*)&g_v[dd * 4];
        p0 += a * v.x; p1 += a * v.y; p2 += a * v.z; p3 += a * v.w;
    }
    // path-quality MLP, hidden unit j = lane (Q_HID == 32)
    float q0 = __ldcs(&pq[e * 4 + 0]) * 0.01f;
    float q1 = __ldcs(&pq[e * 4 + 1]) * 0.01f;
    float q2 = __ldcs(&pq[e * 4 + 2]) * 100.f;
    float q3 = __ldcs(&pq[e * 4 + 3]) * 100.f;
    float hj = q0 * Wq1[lane] + q1 * Wq1[32 + lane]
             + q2 * Wq1[64 + lane] + q3 * Wq1[96 + lane] + bq1[lane];
    hj = fmaxf(hj, 0.f);
    {
        float4 w = *(const float4*)&g_wq2v[lane * 4];
        p0 += hj * w.x; p1 += hj * w.y; p2 += hj * w.z; p3 += hj * w.w;
    }
    #pragma unroll
    for (int o = 16; o > 0; o >>= 1) {
        p0 += __shfl_xor_sync(0xffffffffu, p0, o);
        p1 += __shfl_xor_sync(0xffffffffu, p1, o);
        p2 += __shfl_xor_sync(0xffffffffu, p2, o);
        p3 += __shfl_xor_sync(0xffffffffu, p3, o);
    }
    if (lane < 4) {
        float pe = (lane == 0) ? p0 : (lane == 1) ? p1 : (lane == 2) ? p2 : p3;
        g_pe[e * HEADS + lane] = pe + g_bq2v[lane];
    }
}

// ---------------- K1: h = x @ W (fp32 compute, fp16 store) + fused a_src/a_dst -
// Block: 256 threads, 16 nodes. Thread t owns output column t.
__global__ void k1_gemm_h(const float* __restrict__ x, const float* __restrict__ W,
                          const float* __restrict__ att_src,
                          const float* __restrict__ att_dst) {
    __shared__ float xs[IN_DIM * 16];   // transposed: xs[k*16 + m]
    __shared__ float s_attn[16][8];     // [m][head(src 0..3) | head(dst 4..7)]
    int t = threadIdx.x;
    int n0 = blockIdx.x * 16;
    #pragma unroll
    for (int u = 0; u < 8; ++u) {
        int i = t + u * 256;
        int m = i >> 7, k = i & 127;
        xs[k * 16 + m] = __ldcs(&x[(n0 + m) * IN_DIM + k]);  // x read exactly once
    }
    if (t < 128) s_attn[t >> 3][t & 7] = 0.f;
    __syncthreads();
    float acc[16];
    #pragma unroll
    for (int m = 0; m < 16; ++m) acc[m] = 0.f;
    #pragma unroll 4
    for (int k = 0; k < IN_DIM; ++k) {
        float w = W[k * HC + t];
        const float4* xp = (const float4*)(&xs[k * 16]);
        float4 a0 = xp[0], a1 = xp[1], a2 = xp[2], a3 = xp[3];
        acc[0]  += a0.x * w; acc[1]  += a0.y * w; acc[2]  += a0.z * w; acc[3]  += a0.w * w;
        acc[4]  += a1.x * w; acc[5]  += a1.y * w; acc[6]  += a1.z * w; acc[7]  += a1.w * w;
        acc[8]  += a2.x * w; acc[9]  += a2.y * w; acc[10] += a2.z * w; acc[11] += a2.w * w;
        acc[12] += a3.x * w; acc[13] += a3.y * w; acc[14] += a3.z * w; acc[15] += a3.w * w;
    }
    // store h as fp16
    #pragma unroll
    for (int m = 0; m < 16; ++m)
        g_hh[(n0 + m) * HC + t] = __float2half_rn(acc[m]);
    // fused attention logits from fp32 accumulators (warp = 32 cols of one head)
    int hd = t >> 6;
    float as_t = att_src[t], ad_t = att_dst[t];   // att laid out [head][64] = [t]
    int lane = t & 31;
    #pragma unroll
    for (int m = 0; m < 16; ++m) {
        float ps = acc[m] * as_t;
        float pd = acc[m] * ad_t;
        #pragma unroll
        for (int o = 16; o > 0; o >>= 1) {
            ps += __shfl_xor_sync(0xffffffffu, ps, o);
            pd += __shfl_xor_sync(0xffffffffu, pd, o);
        }
        if (lane == 0) {
            atomicAdd(&s_attn[m][hd], ps);       // 2 warps per head
            atomicAdd(&s_attn[m][4 + hd], pd);
        }
    }
    __syncthreads();
    if (t < 128) {
        int m = t >> 3, j = t & 7;
        float v = s_attn[m][j];
        if (j < 4) g_asrc[(n0 + m) * HEADS + j] = v;
        else       g_adst[(n0 + m) * HEADS + (j - 4)] = v;
    }
}

// ---------------- K2b: ex = exp(leaky(pe + asrc[src] + adst[dst])), den atomic -
__global__ void k2b_ex() {
    int e = blockIdx.x * blockDim.x + threadIdx.x;
    if (e >= E_EDGES) return;
    int src = g_src[e];
    int dst = g_dst[e];
    float4 pe = *(const float4*)&g_pe[e * 4];
    float4 as = *(const float4*)&g_asrc[src * 4];
    float4 ad = *(const float4*)&g_adst[dst * 4];
    float a0 = pe.x + as.x + ad.x;
    float a1 = pe.y + as.y + ad.y;
    float a2 = pe.z + as.z + ad.z;
    float a3 = pe.w + as.w + ad.w;
    a0 = (a0 > 0.f) ? a0 : NEG_SLOPE * a0;
    a1 = (a1 > 0.f) ? a1 : NEG_SLOPE * a1;
    a2 = (a2 > 0.f) ? a2 : NEG_SLOPE * a2;
    a3 = (a3 > 0.f) ? a3 : NEG_SLOPE * a3;
    float4 ex = make_float4(expf(a0), expf(a1), expf(a2), expf(a3));
    *(float4*)&g_ex[e * 4] = ex;          // max-shift omitted: identical softmax
    atomicAdd((float4*)&g_den[dst * 4], ex);   // vector red (sm_90+)
}

// ---------------- K3: den -> 0.25/den (head-mean folded) ----------------------
__global__ void k3_invden() {
    int i = blockIdx.x * blockDim.x + threadIdx.x;
    if (i >= N_NODES * HEADS) return;
    float d = g_den[i];
    g_den[i] = (d > 0.f) ? 0.25f / d : 0.f;
}

// ---------------- K4: aggregate (warp per edge, fp16 h gather, vec atomics) ---
__global__ void k4_aggregate() {
    int warp = (blockIdx.x * blockDim.x + threadIdx.x) >> 5;
    int lane = threadIdx.x & 31;
    if (warp >= E_EDGES) return;
    int e = warp;
    int src = g_src[e];
    int dst = g_dst[e];

    float4 ex  = *(const float4*)&g_ex[e * 4];      // streamed once
    float4 inv = *(const float4*)&g_den[dst * 4];   // small, L2-resident
    float w0 = ex.x * inv.x;
    float w1 = ex.y * inv.y;
    float w2 = ex.z * inv.z;
    float w3 = ex.w * inv.w;

    // fp16 gather: 4 heads x 128B per warp (1 L2 line each), L2-warm
    const __half2* hb = (const __half2*)&g_hh[src * HC];
    float2 h0 = __half22float2(hb[ 0 + lane]);
    float2 h1 = __half22float2(hb[32 + lane]);
    float2 h2 = __half22float2(hb[64 + lane]);
    float2 h3 = __half22float2(hb[96 + lane]);
    float2 m;
    m.x = w0 * h0.x + w1 * h1.x + w2 * h2.x + w3 * h3.x;
    m.y = w0 * h0.y + w1 * h1.y + w2 * h2.y + w3 * h3.y;
    atomicAdd((float2*)&g_acc[dst * OUT_DIM + lane * 2], m);  // vector red
}

// ---------------- K5: out = relu(x_conv @ Wc[:64] + t)  (4 nodes/block) -------
__global__ void k5_out(const float* __restrict__ Wc,
                       const float* __restrict__ bias,
                       float* __restrict__ out) {
    __shared__ float xc[4][OUT_DIM];
    int t = threadIdx.x;
    int nl = t >> 6, j = t & 63;
    int n = blockIdx.x * 4 + nl;
    xc[nl][j] = g_acc[n * OUT_DIM + j] + bias[j];
    __syncthreads();
    float s = g_t[j];
    #pragma unroll 8
    for (int c = 0; c < OUT_DIM; ++c)
        s += xc[nl][c] * Wc[c * 64 + j];
    out[n * OUT_DIM + j] = fmaxf(s, 0.f);
}

// ---------------- launch ----------------
extern "C" void kernel_launch(void* const* d_in, const int* in_sizes, int n_in,
                              void* d_out, int out_size) {
    const float* x         = (const float*)d_in[0];
    const void*  ei        = d_in[1];                 // int32 or int64, runtime-detected
    const float* edge_attr = (const float*)d_in[2];
    const float* pq        = (const float*)d_in[3];
    const float* ns        = (const float*)d_in[4];
    const float* W         = (const float*)d_in[5];
    const float* att_src   = (const float*)d_in[6];
    const float* att_dst   = (const float*)d_in[7];
    const float* W_edge    = (const float*)d_in[8];
    const float* att_edge  = (const float*)d_in[9];
    const float* bias      = (const float*)d_in[10];
    const float* Wq1       = (const float*)d_in[11];
    const float* bq1       = (const float*)d_in[12];
    const float* Wq2       = (const float*)d_in[13];
    const float* bq2       = (const float*)d_in[14];
    const float* Wc        = (const float*)d_in[15];
    const float* bc        = (const float*)d_in[16];
    float* out = (float*)d_out;

    k_convert<<<(N_NODES * OUT_DIM + 255) / 256, 256>>>(ei);
    k0_precompute<<<1, 256>>>(W_edge, att_edge, Wq2, bq2, ns, Wc, bc);
    k2a_edge<<<E_EDGES / 8, 256>>>(edge_attr, pq, Wq1, bq1);      // stream BEFORE k1
    k1_gemm_h<<<N_NODES / 16, 256>>>(x, W, att_src, att_dst);     // g_h lands in L2
    k2b_ex<<<(E_EDGES + 255) / 256, 256>>>();
    k3_invden<<<(N_NODES * HEADS + 255) / 256, 256>>>();
    k4_aggregate<<<E_EDGES / 8, 256>>>();                          // L2-warm gather
    k5_out<<<N_NODES / 4, 256>>>(Wc, bias, out);
}

// round 8
// speedup vs baseline: 1.3387x; 1.1441x over previous
#include <cuda_runtime.h>
#include <cuda_fp16.h>
#include <cstdint>

#define N_NODES 50000
#define E_EDGES 800000
#define IN_DIM  128
#define OUT_DIM 64
#define HEADS   4
#define HC      256      // HEADS*OUT_DIM
#define Q_HID   32
#define NEG_SLOPE 0.2f

// ---------------- scratch (static device memory; no allocations) ----------------
__device__ __align__(16) __half g_hh[N_NODES * HC];    // 25.6 MB  h = x@W (fp16)
__device__ __align__(16) __half g_xh[N_NODES * IN_DIM]; // 12.8 MB  x in fp16
__device__ __align__(16) __half g_whT2[8 * 256 * 16];   // W^T fp16, chunked [kc][n][16]
__device__ __align__(16) float g_asrc[N_NODES * HEADS];
__device__ __align__(16) float g_adst[N_NODES * HEADS];
__device__ __align__(16) float g_pe[E_EDGES * HEADS];
__device__ __align__(16) float g_ex[E_EDGES * HEADS];
__device__ __align__(16) float g_den[N_NODES * HEADS];  // den, then 0.25/den
__device__ __align__(16) float g_acc[N_NODES * OUT_DIM];
__device__ __align__(16) float g_v[64 * HEADS];
__device__ __align__(16) float g_wq2v[Q_HID * HEADS];
__device__ __align__(16) float g_wsrc[IN_DIM * HEADS];  // W @ att_src  (for exact logits)
__device__ __align__(16) float g_wdst[IN_DIM * HEADS];  // W @ att_dst
__device__ float g_bq2v[HEADS];
__device__ float g_t[OUT_DIM];
__device__ int   g_src[E_EDGES];
__device__ int   g_dst[E_EDGES];

// ---------------- K_convert: detect int32/int64, expand indices, zero acc/den --
__global__ void k_convert(const void* __restrict__ ei) {
    __shared__ int s_is64;
    if (threadIdx.x == 0) {
        const int* p = (const int*)ei;
        int zeros = 0;
        for (int i = 1; i < 256; i += 2) zeros += (p[i] == 0);
        s_is64 = (zeros > 64);
    }
    __syncthreads();
    int i = blockIdx.x * blockDim.x + threadIdx.x;   // grid covers N_NODES*64
    if (i < N_NODES * OUT_DIM) g_acc[i] = 0.f;
    if (i < N_NODES * HEADS)   g_den[i] = 0.f;
    if (i < E_EDGES) {
        if (s_is64) {
            const long long* p = (const long long*)ei;
            g_src[i] = (int)p[i];
            g_dst[i] = (int)p[E_EDGES + i];
        } else {
            const int* p = (const int*)ei;
            g_src[i] = p[i];
            g_dst[i] = p[E_EDGES + i];
        }
    }
}

// ---------------- K0: tiny precomputes (one block, 256 threads) ----------------
__global__ void k0_precompute(const float* __restrict__ W_edge,
                              const float* __restrict__ att_edge,
                              const float* __restrict__ Wq2,
                              const float* __restrict__ bq2,
                              const float* __restrict__ ns,
                              const float* __restrict__ Wc,
                              const float* __restrict__ bc,
                              const float* __restrict__ W,
                              const float* __restrict__ att_src,
                              const float* __restrict__ att_dst) {
    int t = threadIdx.x;
    {   // v[d][hd] = sum_c W_edge[d, hd*64+c] * att_edge[hd, c]
        int d = t >> 2, hd = t & 3;
        float s = 0.f;
        #pragma unroll 8
        for (int c = 0; c < 64; ++c)
            s += W_edge[d * HC + hd * 64 + c] * att_edge[hd * 64 + c];
        g_v[t] = s;
    }
    {   // exact-logit fold: wsrc[k][hd] = sum_c W[k, hd*64+c]*att_src[hd,c]
        int k = t & 127, h2 = t >> 7;   // h2 in {0,1}
        #pragma unroll
        for (int rep = 0; rep < 2; ++rep) {
            int hd = h2 + rep * 2;
            float ss = 0.f, sd = 0.f;
            #pragma unroll 8
            for (int c = 0; c < 64; ++c) {
                float w = W[k * HC + hd * 64 + c];
                ss += w * att_src[hd * 64 + c];
                sd += w * att_dst[hd * 64 + c];
            }
            g_wsrc[k * 4 + hd] = ss;
            g_wdst[k * 4 + hd] = sd;
        }
    }
    __syncthreads();
    if (t < Q_HID * HEADS) {   // Wq2v[j][hd] = sum_d Wq2[j,d] * v[d][hd]
        int j = t >> 2, hd = t & 3;
        float s = 0.f;
        #pragma unroll 8
        for (int d = 0; d < 64; ++d)
            s += Wq2[j * 64 + d] * g_v[d * 4 + hd];
        g_wq2v[t] = s;
    }
    if (t >= 128 && t < 128 + HEADS) {
        int hd = t - 128;
        float s = 0.f;
        for (int d = 0; d < 64; ++d) s += bq2[d] * g_v[d * 4 + hd];
        g_bq2v[hd] = s;
    }
    if (t >= 192) {            // t[j] = bc[j] + sum_k ns[k]*Wc[64+k, j]
        int j = t - 192;
        float s = bc[j];
        #pragma unroll
        for (int k = 0; k < 8; ++k) s += ns[k] * Wc[(64 + k) * 64 + j];
        g_t[j] = s;
    }
}

// ---------------- K_wcvt: W -> fp16, transposed + chunked [kc][n][ki] ----------
__global__ void k_wcvt(const float* __restrict__ W) {
    int i = blockIdx.x * blockDim.x + threadIdx.x;   // 32768
    if (i >= 8 * 256 * 16) return;
    int kc = i >> 12, r = i & 4095;
    int n = r >> 4, ki = r & 15;
    g_whT2[i] = __float2half_rn(W[(kc * 16 + ki) * HC + n]);
}

// ---------------- K_xcvt: x -> fp16 + exact fp32 attention logits (warp/node) --
__global__ void k_xcvt(const float* __restrict__ x) {
    int warp = (blockIdx.x * blockDim.x + threadIdx.x) >> 5;
    int lane = threadIdx.x & 31;
    if (warp >= N_NODES) return;
    int n = warp;
    float4 xv = *(const float4*)&x[n * IN_DIM + lane * 4];
    __half2 p0 = __floats2half2_rn(xv.x, xv.y);
    __half2 p1 = __floats2half2_rn(xv.z, xv.w);
    *(uint2*)&g_xh[n * IN_DIM + lane * 4] =
        make_uint2(*(uint32_t*)&p0, *(uint32_t*)&p1);

    float ps0 = 0.f, ps1 = 0.f, ps2 = 0.f, ps3 = 0.f;
    float pd0 = 0.f, pd1 = 0.f, pd2 = 0.f, pd3 = 0.f;
    #pragma unroll
    for (int i = 0; i < 4; ++i) {
        int k = lane * 4 + i;
        float xi = (i == 0) ? xv.x : (i == 1) ? xv.y : (i == 2) ? xv.z : xv.w;
        float4 s = *(const float4*)&g_wsrc[k * 4];
        float4 d = *(const float4*)&g_wdst[k * 4];
        ps0 += xi * s.x; ps1 += xi * s.y; ps2 += xi * s.z; ps3 += xi * s.w;
        pd0 += xi * d.x; pd1 += xi * d.y; pd2 += xi * d.z; pd3 += xi * d.w;
    }
    #pragma unroll
    for (int o = 16; o > 0; o >>= 1) {
        ps0 += __shfl_xor_sync(0xffffffffu, ps0, o);
        ps1 += __shfl_xor_sync(0xffffffffu, ps1, o);
        ps2 += __shfl_xor_sync(0xffffffffu, ps2, o);
        ps3 += __shfl_xor_sync(0xffffffffu, ps3, o);
        pd0 += __shfl_xor_sync(0xffffffffu, pd0, o);
        pd1 += __shfl_xor_sync(0xffffffffu, pd1, o);
        pd2 += __shfl_xor_sync(0xffffffffu, pd2, o);
        pd3 += __shfl_xor_sync(0xffffffffu, pd3, o);
    }
    if (lane < 4) {
        float v = (lane == 0) ? ps0 : (lane == 1) ? ps1 : (lane == 2) ? ps2 : ps3;
        g_asrc[n * 4 + lane] = v;
    } else if (lane < 8) {
        int j = lane - 4;
        float v = (j == 0) ? pd0 : (j == 1) ? pd1 : (j == 2) ? pd2 : pd3;
        g_adst[n * 4 + j] = v;
    }
}

// ---------------- K2a: edge-local logits (stream BEFORE mma fills L2) ---------
__global__ void k2a_edge(const float* __restrict__ edge_attr,
                         const float* __restrict__ pq,
                         const float* __restrict__ Wq1,
                         const float* __restrict__ bq1) {
    int warp = (blockIdx.x * blockDim.x + threadIdx.x) >> 5;
    int lane = threadIdx.x & 31;
    if (warp >= E_EDGES) return;
    int e = warp;

    float p0 = 0.f, p1 = 0.f, p2 = 0.f, p3 = 0.f;
    const float* ea = &edge_attr[(long long)e * 64];
    #pragma unroll
    for (int r = 0; r < 2; ++r) {
        int dd = lane + r * 32;
        float a = __ldcs(&ea[dd]);                 // evict-first stream
        float4 v = *(const float4*)&g_v[dd * 4];
        p0 += a * v.x; p1 += a * v.y; p2 += a * v.z; p3 += a * v.w;
    }
    float q0 = __ldcs(&pq[e * 4 + 0]) * 0.01f;
    float q1 = __ldcs(&pq[e * 4 + 1]) * 0.01f;
    float q2 = __ldcs(&pq[e * 4 + 2]) * 100.f;
    float q3 = __ldcs(&pq[e * 4 + 3]) * 100.f;
    float hj = q0 * Wq1[lane] + q1 * Wq1[32 + lane]
             + q2 * Wq1[64 + lane] + q3 * Wq1[96 + lane] + bq1[lane];
    hj = fmaxf(hj, 0.f);
    {
        float4 w = *(const float4*)&g_wq2v[lane * 4];
        p0 += hj * w.x; p1 += hj * w.y; p2 += hj * w.z; p3 += hj * w.w;
    }
    #pragma unroll
    for (int o = 16; o > 0; o >>= 1) {
        p0 += __shfl_xor_sync(0xffffffffu, p0, o);
        p1 += __shfl_xor_sync(0xffffffffu, p1, o);
        p2 += __shfl_xor_sync(0xffffffffu, p2, o);
        p3 += __shfl_xor_sync(0xffffffffu, p3, o);
    }
    if (lane < 4) {
        float pe = (lane == 0) ? p0 : (lane == 1) ? p1 : (lane == 2) ? p2 : p3;
        g_pe[e * HEADS + lane] = pe + g_bq2v[lane];
    }
}

// ---------------- K2b: ex = exp(leaky(pe + asrc[src] + adst[dst])) + den -------
__global__ void k2b_ex() {
    int e = blockIdx.x * blockDim.x + threadIdx.x;
    if (e >= E_EDGES) return;
    int src = g_src[e];
    int dst = g_dst[e];
    float4 pe = *(const float4*)&g_pe[e * 4];
    float4 as = *(const float4*)&g_asrc[src * 4];
    float4 ad = *(const float4*)&g_adst[dst * 4];
    float a0 = pe.x + as.x + ad.x;
    float a1 = pe.y + as.y + ad.y;
    float a2 = pe.z + as.z + ad.z;
    float a3 = pe.w + as.w + ad.w;
    a0 = (a0 > 0.f) ? a0 : NEG_SLOPE * a0;
    a1 = (a1 > 0.f) ? a1 : NEG_SLOPE * a1;
    a2 = (a2 > 0.f) ? a2 : NEG_SLOPE * a2;
    a3 = (a3 > 0.f) ? a3 : NEG_SLOPE * a3;
    float4 ex = make_float4(expf(a0), expf(a1), expf(a2), expf(a3));
    *(float4*)&g_ex[e * 4] = ex;          // max-shift omitted: identical softmax
    atomicAdd((float4*)&g_den[dst * 4], ex);
}

// ---------------- K3: den -> 0.25/den (head-mean folded) ----------------------
__global__ void k3_invden() {
    int i = blockIdx.x * blockDim.x + threadIdx.x;
    if (i >= N_NODES * HEADS) return;
    float d = g_den[i];
    g_den[i] = (d > 0.f) ? 0.25f / d : 0.f;
}

// ---------------- K1: tensor-core GEMM  g_hh = g_xh @ W  (fp16 in, fp32 acc) --
// Block: 256 thr (8 warps = 2m x 4n). Block tile M=64,N=256,K=128; warp m32 x n64.
__device__ __forceinline__ void mma16816(float* c, const uint32_t* a,
                                         uint32_t b0, uint32_t b1) {
    asm volatile(
        "mma.sync.aligned.m16n8k16.row.col.f32.f16.f16.f32 "
        "{%0,%1,%2,%3}, {%4,%5,%6,%7}, {%8,%9}, {%0,%1,%2,%3};\n"
        : "+f"(c[0]), "+f"(c[1]), "+f"(c[2]), "+f"(c[3])
        : "r"(a[0]), "r"(a[1]), "r"(a[2]), "r"(a[3]), "r"(b0), "r"(b1));
}

__global__ __launch_bounds__(256) void k1_mma() {
    __shared__ __half as[64][136];   // A tile, padded (conflict-free frag loads)
    __shared__ __half ws[256][24];   // W chunk [n][k16], padded
    int t = threadIdx.x, lane = t & 31, w = t >> 5;
    int wm = w & 1, wn = w >> 1;
    int g = lane >> 2, tg = lane & 3;
    int blk = blockIdx.x;

    // stage A tile (64 rows x 128 halves)
    {
        int r = t >> 2, part = t & 3;
        int node = blk * 64 + r;
        uint4 z = make_uint4(0, 0, 0, 0);
        uint4* dst = (uint4*)&as[r][part * 32];
        if (node < N_NODES) {
            const uint4* srcp = (const uint4*)&g_xh[node * IN_DIM + part * 32];
            dst[0] = srcp[0]; dst[1] = srcp[1]; dst[2] = srcp[2]; dst[3] = srcp[3];
        } else {
            dst[0] = z; dst[1] = z; dst[2] = z; dst[3] = z;
        }
    }

    float acc[2][8][4];
    #pragma unroll
    for (int mt = 0; mt < 2; ++mt)
        #pragma unroll
        for (int nt = 0; nt < 8; ++nt)
            #pragma unroll
            for (int i = 0; i < 4; ++i) acc[mt][nt][i] = 0.f;

    for (int kc = 0; kc < 8; ++kc) {
        __syncthreads();
        {   // stage W chunk: contiguous 8KB, fully coalesced
            const uint4* srcp = (const uint4*)&g_whT2[kc * 4096];
            uint4 w0 = srcp[t * 2], w1 = srcp[t * 2 + 1];
            *(uint4*)&ws[t][0] = w0;
            *(uint4*)&ws[t][8] = w1;
        }
        __syncthreads();
        uint32_t a[2][4];
        #pragma unroll
        for (int mt = 0; mt < 2; ++mt) {
            int r = wm * 32 + mt * 16 + g;
            int kb = kc * 16 + tg * 2;
            a[mt][0] = *(const uint32_t*)&as[r][kb];
            a[mt][1] = *(const uint32_t*)&as[r + 8][kb];
            a[mt][2] = *(const uint32_t*)&as[r][kb + 8];
            a[mt][3] = *(const uint32_t*)&as[r + 8][kb + 8];
        }
        #pragma unroll
        for (int nt = 0; nt < 8; ++nt) {
            int n = wn * 64 + nt * 8 + g;
            uint32_t b0 = *(const uint32_t*)&ws[n][tg * 2];
            uint32_t b1 = *(const uint32_t*)&ws[n][tg * 2 + 8];
            mma16816(acc[0][nt], a[0], b0, b1);
            mma16816(acc[1][nt], a[1], b0, b1);
        }
    }
    // epilogue: fp16 store
    #pragma unroll
    for (int mt = 0; mt < 2; ++mt) {
        int r = blk * 64 + wm * 32 + mt * 16 + g;
        #pragma unroll
        for (int nt = 0; nt < 8; ++nt) {
            int col = wn * 64 + nt * 8 + tg * 2;
            if (r < N_NODES) {
                __half2 h01 = __floats2half2_rn(acc[mt][nt][0], acc[mt][nt][1]);
                *(uint32_t*)&g_hh[r * HC + col] = *(uint32_t*)&h01;
            }
            if (r + 8 < N_NODES) {
                __half2 h23 = __floats2half2_rn(acc[mt][nt][2], acc[mt][nt][3]);
                *(uint32_t*)&g_hh[(r + 8) * HC + col] = *(uint32_t*)&h23;
            }
        }
    }
}

// ---------------- K4: aggregate (warp per edge, fp16 L2-warm gather) ----------
__global__ void k4_aggregate() {
    int warp = (blockIdx.x * blockDim.x + threadIdx.x) >> 5;
    int lane = threadIdx.x & 31;
    if (warp >= E_EDGES) return;
    int e = warp;
    int src = g_src[e];
    int dst = g_dst[e];

    float4 ex  = *(const float4*)&g_ex[e * 4];
    float4 inv = *(const float4*)&g_den[dst * 4];
    float w0 = ex.x * inv.x;
    float w1 = ex.y * inv.y;
    float w2 = ex.z * inv.z;
    float w3 = ex.w * inv.w;

    const __half2* hb = (const __half2*)&g_hh[src * HC];
    float2 h0 = __half22float2(hb[ 0 + lane]);
    float2 h1 = __half22float2(hb[32 + lane]);
    float2 h2 = __half22float2(hb[64 + lane]);
    float2 h3 = __half22float2(hb[96 + lane]);
    float2 m;
    m.x = w0 * h0.x + w1 * h1.x + w2 * h2.x + w3 * h3.x;
    m.y = w0 * h0.y + w1 * h1.y + w2 * h2.y + w3 * h3.y;
    atomicAdd((float2*)&g_acc[dst * OUT_DIM + lane * 2], m);
}

// ---------------- K5: out = relu(x_conv @ Wc[:64] + t)  (4 nodes/block) -------
__global__ void k5_out(const float* __restrict__ Wc,
                       const float* __restrict__ bias,
                       float* __restrict__ out) {
    __shared__ float xc[4][OUT_DIM];
    int t = threadIdx.x;
    int nl = t >> 6, j = t & 63;
    int n = blockIdx.x * 4 + nl;
    xc[nl][j] = g_acc[n * OUT_DIM + j] + bias[j];
    __syncthreads();
    float s = g_t[j];
    #pragma unroll 8
    for (int c = 0; c < OUT_DIM; ++c)
        s += xc[nl][c] * Wc[c * 64 + j];
    out[n * OUT_DIM + j] = fmaxf(s, 0.f);
}

// ---------------- launch ----------------
extern "C" void kernel_launch(void* const* d_in, const int* in_sizes, int n_in,
                              void* d_out, int out_size) {
    const float* x         = (const float*)d_in[0];
    const void*  ei        = d_in[1];
    const float* edge_attr = (const float*)d_in[2];
    const float* pq        = (const float*)d_in[3];
    const float* ns        = (const float*)d_in[4];
    const float* W         = (const float*)d_in[5];
    const float* att_src   = (const float*)d_in[6];
    const float* att_dst   = (const float*)d_in[7];
    const float* W_edge    = (const float*)d_in[8];
    const float* att_edge  = (const float*)d_in[9];
    const float* bias      = (const float*)d_in[10];
    const float* Wq1       = (const float*)d_in[11];
    const float* bq1       = (const float*)d_in[12];
    const float* Wq2       = (const float*)d_in[13];
    const float* bq2       = (const float*)d_in[14];
    const float* Wc        = (const float*)d_in[15];
    const float* bc        = (const float*)d_in[16];
    float* out = (float*)d_out;

    k_convert<<<(N_NODES * OUT_DIM + 255) / 256, 256>>>(ei);
    k0_precompute<<<1, 256>>>(W_edge, att_edge, Wq2, bq2, ns, Wc, bc,
                              W, att_src, att_dst);
    k_wcvt<<<(8 * 256 * 16 + 255) / 256, 256>>>(W);
    k2a_edge<<<E_EDGES / 8, 256>>>(edge_attr, pq, Wq1, bq1);   // big stream first
    k_xcvt<<<(N_NODES * 32 + 255) / 256, 256>>>(x);            // fp16 x + exact logits
    k2b_ex<<<(E_EDGES + 255) / 256, 256>>>();
    k3_invden<<<(N_NODES * HEADS + 255) / 256, 256>>>();
    k1_mma<<<(N_NODES + 63) / 64, 256>>>();                    // g_hh lands in L2
    k4_aggregate<<<E_EDGES / 8, 256>>>();                      // L2-warm gather
    k5_out<<<N_NODES / 4, 256>>>(Wc, bias, out);
}

// round 10
// speedup vs baseline: 1.4323x; 1.0699x over previous
#include <cuda_runtime.h>
#include <cuda_fp16.h>
#include <cstdint>

#define N_NODES 50000
#define E_EDGES 800000
#define IN_DIM  128
#define OUT_DIM 64
#define HEADS   4
#define HC      256      // HEADS*OUT_DIM
#define Q_HID   32
#define NEG_SLOPE 0.2f

// ---------------- scratch (static device memory; no allocations) ----------------
__device__ __align__(16) __half g_hh[N_NODES * HC];    // 25.6 MB  h = x@W (fp16)
__device__ __align__(16) __half g_xh[N_NODES * IN_DIM]; // 12.8 MB  x in fp16
__device__ __align__(16) __half g_whT2[8 * 256 * 16];   // W^T fp16, chunked [kc][n][16]
__device__ __align__(16) float g_asrc[N_NODES * HEADS];
__device__ __align__(16) float g_adst[N_NODES * HEADS];
__device__ __align__(16) float g_ex[E_EDGES * HEADS];
__device__ __align__(16) float g_den[N_NODES * HEADS];  // den, then 0.25/den
__device__ __align__(16) float g_acc[N_NODES * OUT_DIM];
__device__ __align__(16) float g_v[64 * HEADS];
__device__ __align__(16) float g_wq2v[Q_HID * HEADS];
__device__ __align__(16) float g_wsrc[IN_DIM * HEADS];  // W @ att_src (exact logits)
__device__ __align__(16) float g_wdst[IN_DIM * HEADS];  // W @ att_dst
__device__ __align__(16) float g_bq2v[HEADS];
__device__ float g_t[OUT_DIM];
__device__ int   g_src[E_EDGES];
__device__ int   g_dst[E_EDGES];

// ---------------- K_convert: detect int32/int64, expand indices, zero acc/den --
__global__ void k_convert(const void* __restrict__ ei) {
    __shared__ int s_is64;
    if (threadIdx.x == 0) {
        const int* p = (const int*)ei;
        int zeros = 0;
        for (int i = 1; i < 256; i += 2) zeros += (p[i] == 0);
        s_is64 = (zeros > 64);
    }
    __syncthreads();
    int i = blockIdx.x * blockDim.x + threadIdx.x;   // grid covers N_NODES*64
    if (i < N_NODES * OUT_DIM) g_acc[i] = 0.f;
    if (i < N_NODES * HEADS)   g_den[i] = 0.f;
    if (i < E_EDGES) {
        if (s_is64) {
            const long long* p = (const long long*)ei;
            g_src[i] = (int)p[i];
            g_dst[i] = (int)p[E_EDGES + i];
        } else {
            const int* p = (const int*)ei;
            g_src[i] = p[i];
            g_dst[i] = p[E_EDGES + i];
        }
    }
}

// ---------------- K0: tiny precomputes (one block, 256 threads) ----------------
__global__ void k0_precompute(const float* __restrict__ W_edge,
                              const float* __restrict__ att_edge,
                              const float* __restrict__ Wq2,
                              const float* __restrict__ bq2,
                              const float* __restrict__ ns,
                              const float* __restrict__ Wc,
                              const float* __restrict__ bc,
                              const float* __restrict__ W,
                              const float* __restrict__ att_src,
                              const float* __restrict__ att_dst) {
    int t = threadIdx.x;
    {   // v[d][hd] = sum_c W_edge[d, hd*64+c] * att_edge[hd, c]
        int d = t >> 2, hd = t & 3;
        float s = 0.f;
        #pragma unroll 8
        for (int c = 0; c < 64; ++c)
            s += W_edge[d * HC + hd * 64 + c] * att_edge[hd * 64 + c];
        g_v[t] = s;
    }
    {   // exact-logit fold: wsrc[k][hd] = sum_c W[k, hd*64+c]*att_src[hd,c]
        int k = t & 127, h2 = t >> 7;   // h2 in {0,1}
        #pragma unroll
        for (int rep = 0; rep < 2; ++rep) {
            int hd = h2 + rep * 2;
            float ss = 0.f, sd = 0.f;
            #pragma unroll 8
            for (int c = 0; c < 64; ++c) {
                float w = W[k * HC + hd * 64 + c];
                ss += w * att_src[hd * 64 + c];
                sd += w * att_dst[hd * 64 + c];
            }
            g_wsrc[k * 4 + hd] = ss;
            g_wdst[k * 4 + hd] = sd;
        }
    }
    __syncthreads();
    if (t < Q_HID * HEADS) {   // Wq2v[j][hd] = sum_d Wq2[j,d] * v[d][hd]
        int j = t >> 2, hd = t & 3;
        float s = 0.f;
        #pragma unroll 8
        for (int d = 0; d < 64; ++d)
            s += Wq2[j * 64 + d] * g_v[d * 4 + hd];
        g_wq2v[t] = s;
    }
    if (t >= 128 && t < 128 + HEADS) {
        int hd = t - 128;
        float s = 0.f;
        for (int d = 0; d < 64; ++d) s += bq2[d] * g_v[d * 4 + hd];
        g_bq2v[hd] = s;
    }
    if (t >= 192) {            // t[j] = bc[j] + sum_k ns[k]*Wc[64+k, j]
        int j = t - 192;
        float s = bc[j];
        #pragma unroll
        for (int k = 0; k < 8; ++k) s += ns[k] * Wc[(64 + k) * 64 + j];
        g_t[j] = s;
    }
}

// ---------------- K_wcvt: W -> fp16, transposed + chunked [kc][n][ki] ----------
__global__ void k_wcvt(const float* __restrict__ W) {
    int i = blockIdx.x * blockDim.x + threadIdx.x;   // 32768
    if (i >= 8 * 256 * 16) return;
    int kc = i >> 12, r = i & 4095;
    int n = r >> 4, ki = r & 15;
    g_whT2[i] = __float2half_rn(W[(kc * 16 + ki) * HC + n]);
}

// ---------------- K_xcvt: x -> fp16 + exact fp32 attention logits (warp/node) --
__global__ void k_xcvt(const float* __restrict__ x) {
    int warp = (blockIdx.x * blockDim.x + threadIdx.x) >> 5;
    int lane = threadIdx.x & 31;
    if (warp >= N_NODES) return;
    int n = warp;
    float4 xv = *(const float4*)&x[n * IN_DIM + lane * 4];
    __half2 p0 = __floats2half2_rn(xv.x, xv.y);
    __half2 p1 = __floats2half2_rn(xv.z, xv.w);
    *(uint2*)&g_xh[n * IN_DIM + lane * 4] =
        make_uint2(*(uint32_t*)&p0, *(uint32_t*)&p1);

    float ps0 = 0.f, ps1 = 0.f, ps2 = 0.f, ps3 = 0.f;
    float pd0 = 0.f, pd1 = 0.f, pd2 = 0.f, pd3 = 0.f;
    #pragma unroll
    for (int i = 0; i < 4; ++i) {
        int k = lane * 4 + i;
        float xi = (i == 0) ? xv.x : (i == 1) ? xv.y : (i == 2) ? xv.z : xv.w;
        float4 s = *(const float4*)&g_wsrc[k * 4];
        float4 d = *(const float4*)&g_wdst[k * 4];
        ps0 += xi * s.x; ps1 += xi * s.y; ps2 += xi * s.z; ps3 += xi * s.w;
        pd0 += xi * d.x; pd1 += xi * d.y; pd2 += xi * d.z; pd3 += xi * d.w;
    }
    #pragma unroll
    for (int o = 16; o > 0; o >>= 1) {
        ps0 += __shfl_xor_sync(0xffffffffu, ps0, o);
        ps1 += __shfl_xor_sync(0xffffffffu, ps1, o);
        ps2 += __shfl_xor_sync(0xffffffffu, ps2, o);
        ps3 += __shfl_xor_sync(0xffffffffu, ps3, o);
        pd0 += __shfl_xor_sync(0xffffffffu, pd0, o);
        pd1 += __shfl_xor_sync(0xffffffffu, pd1, o);
        pd2 += __shfl_xor_sync(0xffffffffu, pd2, o);
        pd3 += __shfl_xor_sync(0xffffffffu, pd3, o);
    }
    if (lane < 4) {
        float v = (lane == 0) ? ps0 : (lane == 1) ? ps1 : (lane == 2) ? ps2 : ps3;
        g_asrc[n * 4 + lane] = v;
    } else if (lane < 8) {
        int j = lane - 4;
        float v = (j == 0) ? pd0 : (j == 1) ? pd1 : (j == 2) ? pd2 : pd3;
        g_adst[n * 4 + j] = v;
    }
}

// ---------------- K2: FUSED edge pass (64 edges/block, 4 lanes/edge) ----------
// Staged coalesced edge_attr -> smem, 4-lane dot + MLP, leaders finish
// alpha -> leaky -> exp -> g_ex + den atomics.
#define EPB 64         // edges per block
#define ROWF 80        // smem row stride in floats (64 data + 16 pad)
__global__ __launch_bounds__(256) void k2_edge(const float* __restrict__ edge_attr,
                                               const float* __restrict__ pq,
                                               const float* __restrict__ Wq1,
                                               const float* __restrict__ bq1) {
    __shared__ float sa[EPB * ROWF];       // 20.5 KB staged edge_attr
    __shared__ float4 spq[EPB];            // path quality per edge
    __shared__ float4 sv[64];              // v table
    __shared__ float4 swq2v[Q_HID];        // Wq2@v table
    __shared__ float  swq1[128], sbq1[Q_HID];

    int t = threadIdx.x;
    int e0 = blockIdx.x * EPB;

    // stage tables
    if (t < 64)       sv[t]      = *(const float4*)&g_v[t * 4];
    else if (t < 96)  swq2v[t - 64] = *(const float4*)&g_wq2v[(t - 64) * 4];
    else if (t < 224) swq1[t - 96]  = Wq1[t - 96];
    else              sbq1[t - 224] = bq1[t - 224];

    // stage edge_attr: 64 edges x 64 floats = 1024 float4, fully coalesced
    {
        const float4* src = (const float4*)&edge_attr[(long long)e0 * 64];
        #pragma unroll
        for (int k = 0; k < 4; ++k) {        // FIX: 4*256 = 1024 float4 (was 16 -> OOB)
            int idx = t + k * 256;           // [0, 1024)
            int row = idx >> 4, col = idx & 15;   // row in [0,64)
            float4 vv = __ldcs(&src[idx]);   // evict-first stream
            *(float4*)&sa[row * ROWF + col * 4] = vv;
        }
    }
    // stage pq (64 x float4, coalesced)
    if (t < EPB) spq[t] = __ldcs(&((const float4*)pq)[e0 + t]);
    __syncthreads();

    int g = t >> 2;          // edge within block [0,64)
    int i = t & 3;           // sub-lane [0,4)
    float p0 = 0.f, p1 = 0.f, p2 = 0.f, p3 = 0.f;

    // main dot: lane i covers float4 cols {i, i+4, i+8, i+12}
    #pragma unroll
    for (int j = 0; j < 4; ++j) {
        int col = i + j * 4;
        float4 a = *(const float4*)&sa[g * ROWF + col * 4];
        int d = col * 4;
        float4 v0 = sv[d], v1 = sv[d + 1], v2 = sv[d + 2], v3 = sv[d + 3];
        p0 += a.x * v0.x + a.y * v1.x + a.z * v2.x + a.w * v3.x;
        p1 += a.x * v0.y + a.y * v1.y + a.z * v2.y + a.w * v3.y;
        p2 += a.x * v0.z + a.y * v1.z + a.z * v2.z + a.w * v3.z;
        p3 += a.x * v0.w + a.y * v1.w + a.z * v2.w + a.w * v3.w;
    }
    // path-quality MLP: lane i handles hidden units [i*8, i*8+8)
    {
        float4 q = spq[g];
        float q0 = q.x * 0.01f, q1 = q.y * 0.01f, q2 = q.z * 100.f, q3 = q.w * 100.f;
        #pragma unroll
        for (int uu = 0; uu < 8; ++uu) {
            int u = i * 8 + uu;
            float hj = q0 * swq1[u] + q1 * swq1[32 + u]
                     + q2 * swq1[64 + u] + q3 * swq1[96 + u] + sbq1[u];
            hj = fmaxf(hj, 0.f);
            float4 w = swq2v[u];
            p0 += hj * w.x; p1 += hj * w.y; p2 += hj * w.z; p3 += hj * w.w;
        }
    }
    // reduce over the 4 sub-lanes (groups are lane-aligned mod 4)
    #pragma unroll
    for (int o = 1; o < 4; o <<= 1) {
        p0 += __shfl_xor_sync(0xffffffffu, p0, o);
        p1 += __shfl_xor_sync(0xffffffffu, p1, o);
        p2 += __shfl_xor_sync(0xffffffffu, p2, o);
        p3 += __shfl_xor_sync(0xffffffffu, p3, o);
    }
    // leaders: finish alpha -> exp -> store + den atomic
    if (i == 0) {
        int e = e0 + g;
        int src = g_src[e];
        int dst = g_dst[e];
        float4 as = *(const float4*)&g_asrc[src * 4];
        float4 ad = *(const float4*)&g_adst[dst * 4];
        float4 bb = *(const float4*)&g_bq2v[0];
        float a0 = p0 + as.x + ad.x + bb.x;
        float a1 = p1 + as.y + ad.y + bb.y;
        float a2 = p2 + as.z + ad.z + bb.z;
        float a3 = p3 + as.w + ad.w + bb.w;
        a0 = (a0 > 0.f) ? a0 : NEG_SLOPE * a0;
        a1 = (a1 > 0.f) ? a1 : NEG_SLOPE * a1;
        a2 = (a2 > 0.f) ? a2 : NEG_SLOPE * a2;
        a3 = (a3 > 0.f) ? a3 : NEG_SLOPE * a3;
        float4 ex = make_float4(expf(a0), expf(a1), expf(a2), expf(a3));
        *(float4*)&g_ex[e * 4] = ex;          // max-shift omitted: identical softmax
        atomicAdd((float4*)&g_den[dst * 4], ex);
    }
}

// ---------------- K3: den -> 0.25/den (head-mean folded) ----------------------
__global__ void k3_invden() {
    int i = blockIdx.x * blockDim.x + threadIdx.x;
    if (i >= N_NODES * HEADS) return;
    float d = g_den[i];
    g_den[i] = (d > 0.f) ? 0.25f / d : 0.f;
}

// ---------------- K1: tensor-core GEMM  g_hh = g_xh @ W  (fp16 in, fp32 acc) --
__device__ __forceinline__ void mma16816(float* c, const uint32_t* a,
                                         uint32_t b0, uint32_t b1) {
    asm volatile(
        "mma.sync.aligned.m16n8k16.row.col.f32.f16.f16.f32 "
        "{%0,%1,%2,%3}, {%4,%5,%6,%7}, {%8,%9}, {%0,%1,%2,%3};\n"
        : "+f"(c[0]), "+f"(c[1]), "+f"(c[2]), "+f"(c[3])
        : "r"(a[0]), "r"(a[1]), "r"(a[2]), "r"(a[3]), "r"(b0), "r"(b1));
}

__global__ __launch_bounds__(256) void k1_mma() {
    __shared__ __half as[64][136];   // A tile, padded
    __shared__ __half ws[256][24];   // W chunk [n][k16], padded
    int t = threadIdx.x, lane = t & 31, w = t >> 5;
    int wm = w & 1, wn = w >> 1;
    int g = lane >> 2, tg = lane & 3;
    int blk = blockIdx.x;

    {   // stage A tile (64 rows x 128 halves)
        int r = t >> 2, part = t & 3;
        int node = blk * 64 + r;
        uint4 z = make_uint4(0, 0, 0, 0);
        uint4* dst = (uint4*)&as[r][part * 32];
        if (node < N_NODES) {
            const uint4* srcp = (const uint4*)&g_xh[node * IN_DIM + part * 32];
            dst[0] = srcp[0]; dst[1] = srcp[1]; dst[2] = srcp[2]; dst[3] = srcp[3];
        } else {
            dst[0] = z; dst[1] = z; dst[2] = z; dst[3] = z;
        }
    }

    float acc[2][8][4];
    #pragma unroll
    for (int mt = 0; mt < 2; ++mt)
        #pragma unroll
        for (int nt = 0; nt < 8; ++nt)
            #pragma unroll
            for (int i = 0; i < 4; ++i) acc[mt][nt][i] = 0.f;

    for (int kc = 0; kc < 8; ++kc) {
        __syncthreads();
        {   // stage W chunk (8KB contiguous, coalesced)
            const uint4* srcp = (const uint4*)&g_whT2[kc * 4096];
            uint4 w0 = srcp[t * 2], w1 = srcp[t * 2 + 1];
            *(uint4*)&ws[t][0] = w0;
            *(uint4*)&ws[t][8] = w1;
        }
        __syncthreads();
        uint32_t a[2][4];
        #pragma unroll
        for (int mt = 0; mt < 2; ++mt) {
            int r = wm * 32 + mt * 16 + g;
            int kb = kc * 16 + tg * 2;
            a[mt][0] = *(const uint32_t*)&as[r][kb];
            a[mt][1] = *(const uint32_t*)&as[r + 8][kb];
            a[mt][2] = *(const uint32_t*)&as[r][kb + 8];
            a[mt][3] = *(const uint32_t*)&as[r + 8][kb + 8];
        }
        #pragma unroll
        for (int nt = 0; nt < 8; ++nt) {
            int n = wn * 64 + nt * 8 + g;
            uint32_t b0 = *(const uint32_t*)&ws[n][tg * 2];
            uint32_t b1 = *(const uint32_t*)&ws[n][tg * 2 + 8];
            mma16816(acc[0][nt], a[0], b0, b1);
            mma16816(acc[1][nt], a[1], b0, b1);
        }
    }
    #pragma unroll
    for (int mt = 0; mt < 2; ++mt) {
        int r = blk * 64 + wm * 32 + mt * 16 + g;
        #pragma unroll
        for (int nt = 0; nt < 8; ++nt) {
            int col = wn * 64 + nt * 8 + tg * 2;
            if (r < N_NODES) {
                __half2 h01 = __floats2half2_rn(acc[mt][nt][0], acc[mt][nt][1]);
                *(uint32_t*)&g_hh[r * HC + col] = *(uint32_t*)&h01;
            }
            if (r + 8 < N_NODES) {
                __half2 h23 = __floats2half2_rn(acc[mt][nt][2], acc[mt][nt][3]);
                *(uint32_t*)&g_hh[(r + 8) * HC + col] = *(uint32_t*)&h23;
            }
        }
    }
}

// ---------------- K4: aggregate (warp per edge, fp16 L2-warm gather) ----------
__global__ void k4_aggregate() {
    int warp = (blockIdx.x * blockDim.x + threadIdx.x) >> 5;
    int lane = threadIdx.x & 31;
    if (warp >= E_EDGES) return;
    int e = warp;
    int src = g_src[e];
    int dst = g_dst[e];

    float4 ex  = *(const float4*)&g_ex[e * 4];
    float4 inv = *(const float4*)&g_den[dst * 4];
    float w0 = ex.x * inv.x;
    float w1 = ex.y * inv.y;
    float w2 = ex.z * inv.z;
    float w3 = ex.w * inv.w;

    const __half2* hb = (const __half2*)&g_hh[src * HC];
    float2 h0 = __half22float2(hb[ 0 + lane]);
    float2 h1 = __half22float2(hb[32 + lane]);
    float2 h2 = __half22float2(hb[64 + lane]);
    float2 h3 = __half22float2(hb[96 + lane]);
    float2 m;
    m.x = w0 * h0.x + w1 * h1.x + w2 * h2.x + w3 * h3.x;
    m.y = w0 * h0.y + w1 * h1.y + w2 * h2.y + w3 * h3.y;
    atomicAdd((float2*)&g_acc[dst * OUT_DIM + lane * 2], m);
}

// ---------------- K5: out = relu(x_conv @ Wc[:64] + t)  (4 nodes/block) -------
__global__ void k5_out(const float* __restrict__ Wc,
                       const float* __restrict__ bias,
                       float* __restrict__ out) {
    __shared__ float xc[4][OUT_DIM];
    int t = threadIdx.x;
    int nl = t >> 6, j = t & 63;
    int n = blockIdx.x * 4 + nl;
    xc[nl][j] = g_acc[n * OUT_DIM + j] + bias[j];
    __syncthreads();
    float s = g_t[j];
    #pragma unroll 8
    for (int c = 0; c < OUT_DIM; ++c)
        s += xc[nl][c] * Wc[c * 64 + j];
    out[n * OUT_DIM + j] = fmaxf(s, 0.f);
}

// ---------------- launch ----------------
extern "C" void kernel_launch(void* const* d_in, const int* in_sizes, int n_in,
                              void* d_out, int out_size) {
    const float* x         = (const float*)d_in[0];
    const void*  ei        = d_in[1];
    const float* edge_attr = (const float*)d_in[2];
    const float* pq        = (const float*)d_in[3];
    const float* ns        = (const float*)d_in[4];
    const float* W         = (const float*)d_in[5];
    const float* att_src   = (const float*)d_in[6];
    const float* att_dst   = (const float*)d_in[7];
    const float* W_edge    = (const float*)d_in[8];
    const float* att_edge  = (const float*)d_in[9];
    const float* bias      = (const float*)d_in[10];
    const float* Wq1       = (const float*)d_in[11];
    const float* bq1       = (const float*)d_in[12];
    const float* Wq2       = (const float*)d_in[13];
    const float* bq2       = (const float*)d_in[14];
    const float* Wc        = (const float*)d_in[15];
    const float* bc        = (const float*)d_in[16];
    float* out = (float*)d_out;

    k_convert<<<(N_NODES * OUT_DIM + 255) / 256, 256>>>(ei);
    k0_precompute<<<1, 256>>>(W_edge, att_edge, Wq2, bq2, ns, Wc, bc,
                              W, att_src, att_dst);
    k_wcvt<<<(8 * 256 * 16 + 255) / 256, 256>>>(W);
    k_xcvt<<<(N_NODES * 32 + 255) / 256, 256>>>(x);      // logits ready for fused k2
    k2_edge<<<E_EDGES / EPB, 256>>>(edge_attr, pq, Wq1, bq1);  // big stream + exp + den
    k3_invden<<<(N_NODES * HEADS + 255) / 256, 256>>>();
    k1_mma<<<(N_NODES + 63) / 64, 256>>>();              // g_hh lands in L2
    k4_aggregate<<<E_EDGES / 8, 256>>>();                // L2-warm gather
    k5_out<<<N_NODES / 4, 256>>>(Wc, bias, out);
}

// round 11
// speedup vs baseline: 1.7857x; 1.2468x over previous
#include <cuda_runtime.h>
#include <cuda_fp16.h>
#include <cstdint>

#define N_NODES 50000
#define E_EDGES 800000
#define IN_DIM  128
#define OUT_DIM 64
#define HEADS   4
#define HC      256      // HEADS*OUT_DIM
#define Q_HID   32
#define NEG_SLOPE 0.2f

// ---------------- scratch (static device memory; no allocations) ----------------
__device__ __align__(16) __half g_hh[N_NODES * HC];     // 25.6 MB  h = x@W (fp16)
__device__ __align__(16) __half g_xh[N_NODES * IN_DIM]; // 12.8 MB  x in fp16
__device__ __align__(16) __half g_whT2[8 * 256 * 16];   // W^T fp16, chunked [kc][n][16]
__device__ __align__(16) float g_asrc[N_NODES * HEADS];
__device__ __align__(16) float g_adst[N_NODES * HEADS];
__device__ __align__(16) float g_ex[E_EDGES * HEADS];
__device__ __align__(16) float g_den[N_NODES * HEADS];  // den, then 0.25/den
__device__ __align__(16) float g_acc[N_NODES * OUT_DIM];
__device__ __align__(16) float g_v[64 * HEADS];
__device__ __align__(16) float g_wq2v[Q_HID * HEADS];
__device__ __align__(16) float g_bq2v[HEADS];
__device__ float g_t[OUT_DIM];
__device__ int   g_src[E_EDGES];
__device__ int   g_dst[E_EDGES];

// ---------------- K_convert: detect int32/int64, expand indices, zero acc/den --
__global__ void k_convert(const void* __restrict__ ei) {
    __shared__ int s_is64;
    if (threadIdx.x == 0) {
        const int* p = (const int*)ei;
        int zeros = 0;
        for (int i = 1; i < 256; i += 2) zeros += (p[i] == 0);
        s_is64 = (zeros > 64);
    }
    __syncthreads();
    int i = blockIdx.x * blockDim.x + threadIdx.x;   // grid covers N_NODES*64
    if (i < N_NODES * OUT_DIM) g_acc[i] = 0.f;
    if (i < N_NODES * HEADS)   g_den[i] = 0.f;
    if (i < E_EDGES) {
        if (s_is64) {
            const long long* p = (const long long*)ei;
            g_src[i] = (int)p[i];
            g_dst[i] = (int)p[E_EDGES + i];
        } else {
            const int* p = (const int*)ei;
            g_src[i] = p[i];
            g_dst[i] = p[E_EDGES + i];
        }
    }
}

// ---------------- K_wcvt: W -> fp16, transposed + chunked [kc][n][ki] ----------
__global__ void k_wcvt(const float* __restrict__ W) {
    int i = blockIdx.x * blockDim.x + threadIdx.x;   // 32768
    if (i >= 8 * 256 * 16) return;
    int kc = i >> 12, r = i & 4095;
    int n = r >> 4, ki = r & 15;
    g_whT2[i] = __float2half_rn(W[(kc * 16 + ki) * HC + n]);
}

// ---------------- K_xcvt: pure x -> fp16 convert (8 floats/thread) ------------
__global__ void k_xcvt(const float* __restrict__ x) {
    int i = blockIdx.x * blockDim.x + threadIdx.x;   // [0, N*128/8)
    if (i >= N_NODES * IN_DIM / 8) return;
    const float4* xp = (const float4*)x;
    float4 a = __ldcs(&xp[i * 2]);
    float4 b = __ldcs(&xp[i * 2 + 1]);
    __half2 h0 = __floats2half2_rn(a.x, a.y), h1 = __floats2half2_rn(a.z, a.w);
    __half2 h2 = __floats2half2_rn(b.x, b.y), h3 = __floats2half2_rn(b.z, b.w);
    uint4 u;
    u.x = *(uint32_t*)&h0; u.y = *(uint32_t*)&h1;
    u.z = *(uint32_t*)&h2; u.w = *(uint32_t*)&h3;
    *(uint4*)&g_xh[i * 8] = u;
}

// ---------------- K1: tensor-core GEMM + fused EXACT fp32 attention logits ----
__device__ __forceinline__ void mma16816(float* c, const uint32_t* a,
                                         uint32_t b0, uint32_t b1) {
    asm volatile(
        "mma.sync.aligned.m16n8k16.row.col.f32.f16.f16.f32 "
        "{%0,%1,%2,%3}, {%4,%5,%6,%7}, {%8,%9}, {%0,%1,%2,%3};\n"
        : "+f"(c[0]), "+f"(c[1]), "+f"(c[2]), "+f"(c[3])
        : "r"(a[0]), "r"(a[1]), "r"(a[2]), "r"(a[3]), "r"(b0), "r"(b1));
}

__global__ __launch_bounds__(256) void k1_mma(const float* __restrict__ att_src,
                                              const float* __restrict__ att_dst) {
    __shared__ __half as[64][136];   // A tile, padded
    __shared__ __half ws[256][24];   // W chunk [n][k16], padded
    __shared__ float s_att[64][8];   // [row][head: src 0-3 | dst 4-7]
    int t = threadIdx.x, lane = t & 31, w = t >> 5;
    int wm = w & 1, wn = w >> 1;     // wn == head (64-col span)
    int g = lane >> 2, tg = lane & 3;
    int blk = blockIdx.x;

    {   // stage A tile (64 rows x 128 halves)
        int r = t >> 2, part = t & 3;
        int node = blk * 64 + r;
        uint4 z = make_uint4(0, 0, 0, 0);
        uint4* dst = (uint4*)&as[r][part * 32];
        if (node < N_NODES) {
            const uint4* srcp = (const uint4*)&g_xh[node * IN_DIM + part * 32];
            dst[0] = srcp[0]; dst[1] = srcp[1]; dst[2] = srcp[2]; dst[3] = srcp[3];
        } else {
            dst[0] = z; dst[1] = z; dst[2] = z; dst[3] = z;
        }
    }

    float acc[2][8][4];
    #pragma unroll
    for (int mt = 0; mt < 2; ++mt)
        #pragma unroll
        for (int nt = 0; nt < 8; ++nt)
            #pragma unroll
            for (int i = 0; i < 4; ++i) acc[mt][nt][i] = 0.f;

    for (int kc = 0; kc < 8; ++kc) {
        __syncthreads();
        {   // stage W chunk (8KB contiguous, coalesced)
            const uint4* srcp = (const uint4*)&g_whT2[kc * 4096];
            uint4 w0 = srcp[t * 2], w1 = srcp[t * 2 + 1];
            *(uint4*)&ws[t][0] = w0;
            *(uint4*)&ws[t][8] = w1;
        }
        __syncthreads();
        uint32_t a[2][4];
        #pragma unroll
        for (int mt = 0; mt < 2; ++mt) {
            int r = wm * 32 + mt * 16 + g;
            int kb = kc * 16 + tg * 2;
            a[mt][0] = *(const uint32_t*)&as[r][kb];
            a[mt][1] = *(const uint32_t*)&as[r + 8][kb];
            a[mt][2] = *(const uint32_t*)&as[r][kb + 8];
            a[mt][3] = *(const uint32_t*)&as[r + 8][kb + 8];
        }
        #pragma unroll
        for (int nt = 0; nt < 8; ++nt) {
            int n = wn * 64 + nt * 8 + g;
            uint32_t b0 = *(const uint32_t*)&ws[n][tg * 2];
            uint32_t b1 = *(const uint32_t*)&ws[n][tg * 2 + 8];
            mma16816(acc[0][nt], a[0], b0, b1);
            mma16816(acc[1][nt], a[1], b0, b1);
        }
    }

    // ---- fp16 store of h ----
    #pragma unroll
    for (int mt = 0; mt < 2; ++mt) {
        int r = blk * 64 + wm * 32 + mt * 16 + g;
        #pragma unroll
        for (int nt = 0; nt < 8; ++nt) {
            int col = wn * 64 + nt * 8 + tg * 2;
            if (r < N_NODES) {
                __half2 h01 = __floats2half2_rn(acc[mt][nt][0], acc[mt][nt][1]);
                *(uint32_t*)&g_hh[r * HC + col] = *(uint32_t*)&h01;
            }
            if (r + 8 < N_NODES) {
                __half2 h23 = __floats2half2_rn(acc[mt][nt][2], acc[mt][nt][3]);
                *(uint32_t*)&g_hh[(r + 8) * HC + col] = *(uint32_t*)&h23;
            }
        }
    }

    // ---- exact fp32 attention logits from the accumulators ----
    float2 asv[8], adv[8];
    #pragma unroll
    for (int nt = 0; nt < 8; ++nt) {
        int col = wn * 64 + nt * 8 + tg * 2;
        asv[nt] = *(const float2*)&att_src[col];
        adv[nt] = *(const float2*)&att_dst[col];
    }
    #pragma unroll
    for (int mt = 0; mt < 2; ++mt) {
        #pragma unroll
        for (int half = 0; half < 2; ++half) {
            float ps = 0.f, pd = 0.f;
            #pragma unroll
            for (int nt = 0; nt < 8; ++nt) {
                float c0 = acc[mt][nt][half * 2], c1 = acc[mt][nt][half * 2 + 1];
                ps += c0 * asv[nt].x + c1 * asv[nt].y;
                pd += c0 * adv[nt].x + c1 * adv[nt].y;
            }
            // reduce over tg (4 lanes cover the 8 cols of each nt)
            ps += __shfl_xor_sync(0xffffffffu, ps, 1);
            ps += __shfl_xor_sync(0xffffffffu, ps, 2);
            pd += __shfl_xor_sync(0xffffffffu, pd, 1);
            pd += __shfl_xor_sync(0xffffffffu, pd, 2);
            if (tg == 0) {
                int rl = wm * 32 + mt * 16 + g + half * 8;   // unique (rl, wn)
                s_att[rl][wn] = ps;
                s_att[rl][4 + wn] = pd;
            }
        }
    }
    __syncthreads();
    if (t < 64) {
        int node = blk * 64 + t;
        if (node < N_NODES) {
            *(float4*)&g_asrc[node * 4] = *(const float4*)&s_att[t][0];
            *(float4*)&g_adst[node * 4] = *(const float4*)&s_att[t][4];
        }
    }
}

// ---------------- K0: tiny precomputes (one block, 256 threads) ----------------
__global__ void k0_precompute(const float* __restrict__ W_edge,
                              const float* __restrict__ att_edge,
                              const float* __restrict__ Wq2,
                              const float* __restrict__ bq2,
                              const float* __restrict__ ns,
                              const float* __restrict__ Wc,
                              const float* __restrict__ bc) {
    int t = threadIdx.x;
    {   // v[d][hd] = sum_c W_edge[d, hd*64+c] * att_edge[hd, c]
        int d = t >> 2, hd = t & 3;
        float s = 0.f;
        #pragma unroll 8
        for (int c = 0; c < 64; ++c)
            s += W_edge[d * HC + hd * 64 + c] * att_edge[hd * 64 + c];
        g_v[t] = s;
    }
    __syncthreads();
    if (t < Q_HID * HEADS) {   // Wq2v[j][hd] = sum_d Wq2[j,d] * v[d][hd]
        int j = t >> 2, hd = t & 3;
        float s = 0.f;
        #pragma unroll 8
        for (int d = 0; d < 64; ++d)
            s += Wq2[j * 64 + d] * g_v[d * 4 + hd];
        g_wq2v[t] = s;
    }
    if (t >= 128 && t < 128 + HEADS) {
        int hd = t - 128;
        float s = 0.f;
        for (int d = 0; d < 64; ++d) s += bq2[d] * g_v[d * 4 + hd];
        g_bq2v[hd] = s;
    }
    if (t >= 192) {            // t[j] = bc[j] + sum_k ns[k]*Wc[64+k, j]
        int j = t - 192;
        float s = bc[j];
        #pragma unroll
        for (int k = 0; k < 8; ++k) s += ns[k] * Wc[(64 + k) * 64 + j];
        g_t[j] = s;
    }
}

// ---------------- K2: FUSED edge pass (64 edges/block, 4 lanes/edge) ----------
#define EPB 64         // edges per block
#define ROWF 80        // smem row stride in floats (64 data + 16 pad)
__global__ __launch_bounds__(256) void k2_edge(const float* __restrict__ edge_attr,
                                               const float* __restrict__ pq,
                                               const float* __restrict__ Wq1,
                                               const float* __restrict__ bq1) {
    __shared__ float sa[EPB * ROWF];       // 20.5 KB staged edge_attr
    __shared__ float4 spq[EPB];            // path quality per edge
    __shared__ float4 sv[64];              // v table
    __shared__ float4 swq2v[Q_HID];        // Wq2@v table
    __shared__ float  swq1[128], sbq1[Q_HID];

    int t = threadIdx.x;
    int e0 = blockIdx.x * EPB;

    // stage tables
    if (t < 64)       sv[t]      = *(const float4*)&g_v[t * 4];
    else if (t < 96)  swq2v[t - 64] = *(const float4*)&g_wq2v[(t - 64) * 4];
    else if (t < 224) swq1[t - 96]  = Wq1[t - 96];
    else              sbq1[t - 224] = bq1[t - 224];

    // stage edge_attr: 64 edges x 64 floats = 1024 float4, fully coalesced
    {
        const float4* src = (const float4*)&edge_attr[(long long)e0 * 64];
        #pragma unroll
        for (int k = 0; k < 4; ++k) {
            int idx = t + k * 256;           // [0, 1024)
            int row = idx >> 4, col = idx & 15;
            float4 vv = __ldcs(&src[idx]);   // evict-first stream
            *(float4*)&sa[row * ROWF + col * 4] = vv;
        }
    }
    if (t < EPB) spq[t] = __ldcs(&((const float4*)pq)[e0 + t]);
    __syncthreads();

    int g = t >> 2;          // edge within block [0,64)
    int i = t & 3;           // sub-lane [0,4)
    float p0 = 0.f, p1 = 0.f, p2 = 0.f, p3 = 0.f;

    #pragma unroll
    for (int j = 0; j < 4; ++j) {
        int col = i + j * 4;
        float4 a = *(const float4*)&sa[g * ROWF + col * 4];
        int d = col * 4;
        float4 v0 = sv[d], v1 = sv[d + 1], v2 = sv[d + 2], v3 = sv[d + 3];
        p0 += a.x * v0.x + a.y * v1.x + a.z * v2.x + a.w * v3.x;
        p1 += a.x * v0.y + a.y * v1.y + a.z * v2.y + a.w * v3.y;
        p2 += a.x * v0.z + a.y * v1.z + a.z * v2.z + a.w * v3.z;
        p3 += a.x * v0.w + a.y * v1.w + a.z * v2.w + a.w * v3.w;
    }
    {
        float4 q = spq[g];
        float q0 = q.x * 0.01f, q1 = q.y * 0.01f, q2 = q.z * 100.f, q3 = q.w * 100.f;
        #pragma unroll
        for (int uu = 0; uu < 8; ++uu) {
            int u = i * 8 + uu;
            float hj = q0 * swq1[u] + q1 * swq1[32 + u]
                     + q2 * swq1[64 + u] + q3 * swq1[96 + u] + sbq1[u];
            hj = fmaxf(hj, 0.f);
            float4 w = swq2v[u];
            p0 += hj * w.x; p1 += hj * w.y; p2 += hj * w.z; p3 += hj * w.w;
        }
    }
    #pragma unroll
    for (int o = 1; o < 4; o <<= 1) {
        p0 += __shfl_xor_sync(0xffffffffu, p0, o);
        p1 += __shfl_xor_sync(0xffffffffu, p1, o);
        p2 += __shfl_xor_sync(0xffffffffu, p2, o);
        p3 += __shfl_xor_sync(0xffffffffu, p3, o);
    }
    if (i == 0) {
        int e = e0 + g;
        int src = g_src[e];
        int dst = g_dst[e];
        float4 as = *(const float4*)&g_asrc[src * 4];
        float4 ad = *(const float4*)&g_adst[dst * 4];
        float4 bb = *(const float4*)&g_bq2v[0];
        float a0 = p0 + as.x + ad.x + bb.x;
        float a1 = p1 + as.y + ad.y + bb.y;
        float a2 = p2 + as.z + ad.z + bb.z;
        float a3 = p3 + as.w + ad.w + bb.w;
        a0 = (a0 > 0.f) ? a0 : NEG_SLOPE * a0;
        a1 = (a1 > 0.f) ? a1 : NEG_SLOPE * a1;
        a2 = (a2 > 0.f) ? a2 : NEG_SLOPE * a2;
        a3 = (a3 > 0.f) ? a3 : NEG_SLOPE * a3;
        float4 ex = make_float4(expf(a0), expf(a1), expf(a2), expf(a3));
        *(float4*)&g_ex[e * 4] = ex;          // max-shift omitted: identical softmax
        atomicAdd((float4*)&g_den[dst * 4], ex);
    }
}

// ---------------- K3: den -> 0.25/den (head-mean folded) ----------------------
__global__ void k3_invden() {
    int i = blockIdx.x * blockDim.x + threadIdx.x;
    if (i >= N_NODES * HEADS) return;
    float d = g_den[i];
    g_den[i] = (d > 0.f) ? 0.25f / d : 0.f;
}

// ---------------- K4: aggregate (HALF-warp per edge, float4 atomics) ----------
__global__ void k4_aggregate() {
    int gid = blockIdx.x * blockDim.x + threadIdx.x;
    int e = gid >> 4;              // half-warp per edge
    if (e >= E_EDGES) return;
    int l = gid & 15;              // lane within half-warp
    int src = g_src[e];
    int dst = g_dst[e];

    float4 ex  = *(const float4*)&g_ex[e * 4];
    float4 inv = *(const float4*)&g_den[dst * 4];
    float w0 = ex.x * inv.x;
    float w1 = ex.y * inv.y;
    float w2 = ex.z * inv.z;
    float w3 = ex.w * inv.w;

    int c0 = l * 4;                // 4 channels per lane
    const __half* hb = &g_hh[src * HC];
    uint2 u0 = *(const uint2*)&hb[c0];
    uint2 u1 = *(const uint2*)&hb[64 + c0];
    uint2 u2 = *(const uint2*)&hb[128 + c0];
    uint2 u3 = *(const uint2*)&hb[192 + c0];
    float2 a0 = __half22float2(*(__half2*)&u0.x), b0 = __half22float2(*(__half2*)&u0.y);
    float2 a1 = __half22float2(*(__half2*)&u1.x), b1 = __half22float2(*(__half2*)&u1.y);
    float2 a2 = __half22float2(*(__half2*)&u2.x), b2 = __half22float2(*(__half2*)&u2.y);
    float2 a3 = __half22float2(*(__half2*)&u3.x), b3 = __half22float2(*(__half2*)&u3.y);

    float4 m;
    m.x = w0 * a0.x + w1 * a1.x + w2 * a2.x + w3 * a3.x;
    m.y = w0 * a0.y + w1 * a1.y + w2 * a2.y + w3 * a3.y;
    m.z = w0 * b0.x + w1 * b1.x + w2 * b2.x + w3 * b3.x;
    m.w = w0 * b0.y + w1 * b1.y + w2 * b2.y + w3 * b3.y;
    atomicAdd((float4*)&g_acc[dst * OUT_DIM + c0], m);
}

// ---------------- K5: out = relu(x_conv @ Wc[:64] + t)  (4 nodes/block) -------
__global__ void k5_out(const float* __restrict__ Wc,
                       const float* __restrict__ bias,
                       float* __restrict__ out) {
    __shared__ float xc[4][OUT_DIM];
    int t = threadIdx.x;
    int nl = t >> 6, j = t & 63;
    int n = blockIdx.x * 4 + nl;
    xc[nl][j] = g_acc[n * OUT_DIM + j] + bias[j];
    __syncthreads();
    float s = g_t[j];
    #pragma unroll 8
    for (int c = 0; c < OUT_DIM; ++c)
        s += xc[nl][c] * Wc[c * 64 + j];
    out[n * OUT_DIM + j] = fmaxf(s, 0.f);
}

// ---------------- launch ----------------
extern "C" void kernel_launch(void* const* d_in, const int* in_sizes, int n_in,
                              void* d_out, int out_size) {
    const float* x         = (const float*)d_in[0];
    const void*  ei        = d_in[1];
    const float* edge_attr = (const float*)d_in[2];
    const float* pq        = (const float*)d_in[3];
    const float* ns        = (const float*)d_in[4];
    const float* W         = (const float*)d_in[5];
    const float* att_src   = (const float*)d_in[6];
    const float* att_dst   = (const float*)d_in[7];
    const float* W_edge    = (const float*)d_in[8];
    const float* att_edge  = (const float*)d_in[9];
    const float* bias      = (const float*)d_in[10];
    const float* Wq1       = (const float*)d_in[11];
    const float* bq1       = (const float*)d_in[12];
    const float* Wq2       = (const float*)d_in[13];
    const float* bq2       = (const float*)d_in[14];
    const float* Wc        = (const float*)d_in[15];
    const float* bc        = (const float*)d_in[16];
    float* out = (float*)d_out;

    k_convert<<<(N_NODES * OUT_DIM + 255) / 256, 256>>>(ei);            // idx 0
    k_wcvt<<<(8 * 256 * 16 + 255) / 256, 256>>>(W);                     // idx 1
    k_xcvt<<<(N_NODES * IN_DIM / 8 + 255) / 256, 256>>>(x);             // idx 2
    k1_mma<<<(N_NODES + 63) / 64, 256>>>(att_src, att_dst);             // idx 3 (profiled)
    k0_precompute<<<1, 256>>>(W_edge, att_edge, Wq2, bq2, ns, Wc, bc);  // idx 4
    k2_edge<<<E_EDGES / EPB, 256>>>(edge_attr, pq, Wq1, bq1);           // idx 5 (ldcs streams)
    k3_invden<<<(N_NODES * HEADS + 255) / 256, 256>>>();                // idx 6
    k4_aggregate<<<(E_EDGES * 16 + 255) / 256, 256>>>();                // idx 7
    k5_out<<<N_NODES / 4, 256>>>(Wc, bias, out);                        // idx 8
}